// round 12
// baseline (speedup 1.0000x reference)
#include <cuda_runtime.h>
#include <cuda_bf16.h>
#include <cstdint>

// ---------------- problem constants ----------------
#define O_N   3
#define DK    128
#define DV    512
#define BANK  8192
#define QN    4096
#define MQ    64             // queries per block
#define BN    64             // bank tile
#define NV    256            // v columns per pass (vpass = blockIdx.z)
#define NT    128            // bank tiles (8192/64)
#define THREADS 256
// 1/sqrt(128) * log2(e), folded into Q so epilogue is bare ex2
#define QSCALE (0.08838834764831845f * 1.4426950408889634f)

// ---------------- smem layout ----------------
// strides in bf16 halves; (row_stride_bytes/16) mod 8 odd -> ldmatrix conflict-free
#define QS_STR 136   // 272 B rows
#define KS_STR 136
#define VS_STR 72    // 144 B rows
#define PS_STR 72
#define QS_OFF     0                         // 64*136*2  = 17408
#define KS_OFF(b)  (17408 + (b) * 17408)     // x2 -> 52224
#define VS_OFF(b)  (52224 + (b) * 36864)     // x3 -> 162816 (TRIPLE buffered)
#define PS_OFF(b)  (162816 + (b) * 9216)     // x2 -> 181248 (DOUBLE buffered)
#define LROW_OFF   181248                    // 64 f32 = 256 -> 181504
#define SMEM_BYTES 181504

// ---------------- helpers ----------------
static __device__ __forceinline__ uint32_t s2u(const void* p) {
    uint32_t a;
    asm("{ .reg .u64 t; cvta.to.shared.u64 t, %1; cvt.u32.u64 %0, t; }" : "=r"(a) : "l"(p));
    return a;
}
static __device__ __forceinline__ uint32_t pack2(float lo, float hi) {   // lo -> low half
    uint32_t r;
    asm("cvt.rn.bf16x2.f32 %0, %1, %2;" : "=r"(r) : "f"(hi), "f"(lo));
    return r;
}
static __device__ __forceinline__ float ex2f(float x) {
    float r; asm("ex2.approx.f32 %0, %1;" : "=f"(r) : "f"(x)); return r;
}
static __device__ __forceinline__ void ldsm4(uint32_t* r, uint32_t addr) {
    asm volatile("ldmatrix.sync.aligned.m8n8.x4.shared.b16 {%0,%1,%2,%3}, [%4];"
                 : "=r"(r[0]), "=r"(r[1]), "=r"(r[2]), "=r"(r[3]) : "r"(addr));
}
static __device__ __forceinline__ void mma16816(float* d, const uint32_t* a,
                                                uint32_t b0, uint32_t b1) {
    asm volatile(
        "mma.sync.aligned.m16n8k16.row.col.f32.bf16.bf16.f32 "
        "{%0,%1,%2,%3}, {%4,%5,%6,%7}, {%8,%9}, {%0,%1,%2,%3};"
        : "+f"(d[0]), "+f"(d[1]), "+f"(d[2]), "+f"(d[3])
        : "r"(a[0]), "r"(a[1]), "r"(a[2]), "r"(a[3]), "r"(b0), "r"(b1));
}

// ---------------- tile loader (all 256 threads, direct LDG->cvt->STS) ----------------
static __device__ __forceinline__ void load_tile(unsigned char* smem,
                                                 const float* __restrict__ kg,
                                                 const float* __restrict__ vg,
                                                 int kbuf, int vbuf, int t, int tid) {
    const int n0 = t * BN;
    unsigned char* ks = smem + KS_OFF(kbuf);
    unsigned char* vs = smem + VS_OFF(vbuf);
    // K: gmem keys[k][n] fp32 -> Ks[n][k] bf16 (pairs packed along k)
#pragma unroll
    for (int i = 0; i < 4; ++i) {
        int idx = tid + THREADS * i;
        int k2 = idx >> 4, n4 = (idx & 15) * 4;
        const float4 xlo = *(const float4*)(kg + (size_t)(2 * k2) * BANK + n0 + n4);
        const float4 xhi = *(const float4*)(kg + (size_t)(2 * k2 + 1) * BANK + n0 + n4);
        *(uint32_t*)(ks + ((n4 + 0) * KS_STR + 2 * k2) * 2) = pack2(xlo.x, xhi.x);
        *(uint32_t*)(ks + ((n4 + 1) * KS_STR + 2 * k2) * 2) = pack2(xlo.y, xhi.y);
        *(uint32_t*)(ks + ((n4 + 2) * KS_STR + 2 * k2) * 2) = pack2(xlo.z, xhi.z);
        *(uint32_t*)(ks + ((n4 + 3) * KS_STR + 2 * k2) * 2) = pack2(xlo.w, xhi.w);
    }
    // V: gmem values[v][n] fp32 -> Vs[v][n] bf16 (convert only)
#pragma unroll
    for (int i = 0; i < 16; ++i) {
        int idx = tid + THREADS * i;
        int v = idx >> 4, n4 = (idx & 15) * 4;
        const float4 x = *(const float4*)(vg + (size_t)v * BANK + n0 + n4);
        uint2 pk;
        pk.x = pack2(x.x, x.y);
        pk.y = pack2(x.z, x.w);
        *(uint2*)(vs + (v * VS_STR + n4) * 2) = pk;
    }
}

// ---------------- main fused kernel ----------------
__global__ __launch_bounds__(THREADS)
void attn_mma_kernel(const float* __restrict__ keys, const float* __restrict__ values,
                     const float* __restrict__ q_in, float* __restrict__ out) {
    extern __shared__ unsigned char smem[];
    const uint32_t sb = s2u(smem);
    const int tid = threadIdx.x;
    const int l = tid & 31;
    const int wid = tid >> 5;
    const int mw = wid >> 2;          // 0..1 : 32-query group
    const int nw = wid & 3;           // 0..3 : QK n-group (16) / PV v-group (64)
    const int o = blockIdx.y;
    const int q0 = blockIdx.x * MQ;
    const int v0 = blockIdx.z * NV;

    const float* kg = keys + (size_t)o * DK * BANK;
    const float* vg = values + (size_t)o * DV * BANK + (size_t)v0 * BANK;

    if (tid < MQ) *(float*)(smem + LROW_OFF + tid * 4) = 0.0f;

    // Q -> Qs[q][k] bf16, scaled (one-time)
    {
        __nv_bfloat16* qs = (__nv_bfloat16*)(smem + QS_OFF);
#pragma unroll
        for (int i = 0; i < 8; ++i) {
            int idx = tid + THREADS * i;
            int k = idx >> 4, q4 = (idx & 15) * 4;
            const float4 x = *(const float4*)(q_in + (size_t)k * QN + q0 + q4);
            qs[(q4 + 0) * QS_STR + k] = __float2bfloat16(x.x * QSCALE);
            qs[(q4 + 1) * QS_STR + k] = __float2bfloat16(x.y * QSCALE);
            qs[(q4 + 2) * QS_STR + k] = __float2bfloat16(x.z * QSCALE);
            qs[(q4 + 3) * QS_STR + k] = __float2bfloat16(x.w * QSCALE);
        }
    }
    load_tile(smem, kg, vg, 0, 0, 0, tid);   // tile 0 -> Ks[0], Vs[0]
    __syncthreads();

    float acc[2][8][4];
#pragma unroll
    for (int a = 0; a < 2; ++a)
#pragma unroll
        for (int b = 0; b < 8; ++b)
#pragma unroll
            for (int c = 0; c < 4; ++c) acc[a][b][c] = 0.0f;
    float lsum[4] = {0.f, 0.f, 0.f, 0.f};

    // ldmatrix lane address components
    const int aRow = l & 15;                     // A frags: rows within m16
    const int aKhi = l >> 4;                     // A frags: k-half select
    const int bRow = (l & 7) + ((l >> 4) << 3);  // B frags: rows (n-dim of B^T)
    const int bKhi = (l >> 3) & 1;               // B frags: k-half select

    const uint32_t qsb = sb + QS_OFF + (uint32_t)(((mw * 32 + aRow) * QS_STR + 8 * aKhi) * 2);
    const uint32_t pA  = (uint32_t)(((mw * 32 + aRow) * PS_STR + 8 * aKhi) * 2);   // A-frag offset in Ps
    const uint32_t pW  = (uint32_t)((nw * 16) * 2);                                 // exp write col base
    const uint32_t vB  = (uint32_t)(((nw * 64 + bRow) * VS_STR + 8 * bKhi) * 2);   // B-frag offset in Vs
    const uint32_t kB  = (uint32_t)(((nw * 16 + bRow) * KS_STR + 8 * bKhi) * 2);
    const int g8 = l >> 2, t2 = (l & 3) * 2;

    int vcur = 0, vnext = 1, vprev = 2;   // rotating Vs buffer indices (tile g -> g%3)

    for (int g = 0; g < NT; ++g) {
        const uint32_t ksb  = sb + KS_OFF(g & 1) + kB;
        const uint32_t psbP = sb + PS_OFF((g + 1) & 1) + pA;   // Ps of tile g-1
        const uint32_t vsbP = sb + VS_OFF(vprev) + vB;         // Vs of tile g-1

        // ---- interleaved: QK(g) [8 k-steps] with PV(g-1) [4 kg-steps] ----
        float sc[2][2][4];
#pragma unroll
        for (int a = 0; a < 2; ++a)
#pragma unroll
            for (int b = 0; b < 2; ++b)
#pragma unroll
                for (int c = 0; c < 4; ++c) sc[a][b][c] = 0.0f;

#pragma unroll
        for (int s = 0; s < 8; ++s) {
            {   // QK k-step s
                uint32_t a0[4], a1[4], b[4];
                ldsm4(a0, qsb + s * 32);
                ldsm4(a1, qsb + 16 * QS_STR * 2 + s * 32);
                ldsm4(b, ksb + s * 32);
                mma16816(sc[0][0], a0, b[0], b[1]);
                mma16816(sc[0][1], a0, b[2], b[3]);
                mma16816(sc[1][0], a1, b[0], b[1]);
                mma16816(sc[1][1], a1, b[2], b[3]);
            }
            if ((s & 1) && g > 0) {   // PV kg-step for tile g-1
                const int kgs = s >> 1;
                uint32_t a0[4], a1[4];
                ldsm4(a0, psbP + kgs * 32);
                ldsm4(a1, psbP + 16 * PS_STR * 2 + kgs * 32);
#pragma unroll
                for (int j = 0; j < 4; ++j) {
                    uint32_t b[4];
                    ldsm4(b, vsbP + (uint32_t)(j * 16 * VS_STR * 2) + kgs * 32);
                    mma16816(acc[0][2 * j],     a0, b[0], b[1]);
                    mma16816(acc[0][2 * j + 1], a0, b[2], b[3]);
                    mma16816(acc[1][2 * j],     a1, b[0], b[1]);
                    mma16816(acc[1][2 * j + 1], a1, b[2], b[3]);
                }
            }
        }

        // ---- exp -> Ps[g&1] (bf16), lsum partials ----
        {
            unsigned char* psw = smem + PS_OFF(g & 1);
#pragma unroll
            for (int mf = 0; mf < 2; ++mf)
#pragma unroll
                for (int nf = 0; nf < 2; ++nf) {
                    const int col = nw * 16 + nf * 8 + t2;
                    const int row = mw * 32 + mf * 16 + g8;
                    float p0 = ex2f(sc[mf][nf][0]), p1 = ex2f(sc[mf][nf][1]);
                    *(uint32_t*)(psw + ((size_t)row * PS_STR + col) * 2) = pack2(p0, p1);
                    float p2 = ex2f(sc[mf][nf][2]), p3 = ex2f(sc[mf][nf][3]);
                    *(uint32_t*)(psw + ((size_t)(row + 8) * PS_STR + col) * 2) = pack2(p2, p3);
                    lsum[mf * 2 + 0] += p0 + p1;
                    lsum[mf * 2 + 1] += p2 + p3;
                }
        }

        // ---- loader: tile g+1 -> Ks[(g+1)&1], Vs[vnext] ----
        if (g + 1 < NT) load_tile(smem, kg, vg, (g + 1) & 1, vnext, g + 1, tid);
        __syncthreads();   // single barrier per tile

        vprev = vcur; vcur = vnext; vnext = (vnext + 1 == 3) ? 0 : vnext + 1;
    }

    // ---- drain: PV for the last tile (Ps[(NT-1)&1], Vs[(NT-1)%3] = vprev) ----
    {
        const uint32_t psbP = sb + PS_OFF((NT - 1) & 1) + pA;
        const uint32_t vsbP = sb + VS_OFF(vprev) + vB;
#pragma unroll
        for (int kgs = 0; kgs < 4; ++kgs) {
            uint32_t a0[4], a1[4];
            ldsm4(a0, psbP + kgs * 32);
            ldsm4(a1, psbP + 16 * PS_STR * 2 + kgs * 32);
#pragma unroll
            for (int j = 0; j < 4; ++j) {
                uint32_t b[4];
                ldsm4(b, vsbP + (uint32_t)(j * 16 * VS_STR * 2) + kgs * 32);
                mma16816(acc[0][2 * j],     a0, b[0], b[1]);
                mma16816(acc[0][2 * j + 1], a0, b[2], b[3]);
                mma16816(acc[1][2 * j],     a1, b[0], b[1]);
                mma16816(acc[1][2 * j + 1], a1, b[2], b[3]);
            }
        }
    }

    // ---- reduce l across lanes (t bits) then warps (shared atomics) ----
#pragma unroll
    for (int j = 0; j < 4; ++j) {
        lsum[j] += __shfl_xor_sync(0xffffffffu, lsum[j], 1);
        lsum[j] += __shfl_xor_sync(0xffffffffu, lsum[j], 2);
    }
    if ((l & 3) == 0) {
        float* lrow = (float*)(smem + LROW_OFF);
#pragma unroll
        for (int j = 0; j < 4; ++j)
            atomicAdd(&lrow[mw * 32 + (j >> 1) * 16 + g8 + 8 * (j & 1)], lsum[j]);
    }
    __syncthreads();

    // ---- normalize + store ----
    const float* lrow = (const float*)(smem + LROW_OFF);
    float inv[4];
#pragma unroll
    for (int j = 0; j < 4; ++j)
        inv[j] = 1.0f / lrow[mw * 32 + (j >> 1) * 16 + g8 + 8 * (j & 1)];

    float* ob = out + (size_t)o * 1024 * QN + (size_t)v0 * QN + q0;
#pragma unroll
    for (int mf = 0; mf < 2; ++mf)
#pragma unroll
        for (int nf = 0; nf < 8; ++nf) {
            const int col = nw * 64 + nf * 8 + t2;
            const int r0 = mw * 32 + mf * 16 + g8;
            ob[(size_t)col * QN + r0]           = acc[mf][nf][0] * inv[mf * 2];
            ob[(size_t)(col + 1) * QN + r0]     = acc[mf][nf][1] * inv[mf * 2];
            ob[(size_t)col * QN + r0 + 8]       = acc[mf][nf][2] * inv[mf * 2 + 1];
            ob[(size_t)(col + 1) * QN + r0 + 8] = acc[mf][nf][3] * inv[mf * 2 + 1];
        }
}

// ---------------- q_out broadcast (channels [512,1024) per object) ----------------
__global__ void copy_qout_kernel(const float* __restrict__ qo, float* __restrict__ out) {
    size_t i = (size_t)blockIdx.x * blockDim.x + threadIdx.x;  // over DV*QN/4
    const float4 v = reinterpret_cast<const float4*>(qo)[i];
#pragma unroll
    for (int o = 0; o < O_N; ++o)
        reinterpret_cast<float4*>(out + (size_t)o * 1024 * QN + (size_t)DV * QN)[i] = v;
}

extern "C" void kernel_launch(void* const* d_in, const int* in_sizes, int n_in,
                              void* d_out, int out_size) {
    const float* keys   = (const float*)d_in[0];  // [3,128,8192]
    const float* values = (const float*)d_in[1];  // [3,512,8192]
    const float* q_in   = (const float*)d_in[2];  // [1,128,4096]
    const float* q_out  = (const float*)d_in[3];  // [1,512,4096]
    float* out = (float*)d_out;                   // [1,3,1024,4096]

    (void)cudaFuncSetAttribute(attn_mma_kernel,
                               cudaFuncAttributeMaxDynamicSharedMemorySize, SMEM_BYTES);

    // copy_qout FIRST (disjoint output slab) so ncu's "-s 5" lands on attn_mma_kernel.
    copy_qout_kernel<<<(DV * QN / 4) / 256, 256>>>(q_out, out);

    dim3 grid(QN / MQ, O_N, DV / NV);   // 64 x 3 x 2 = 384 blocks
    attn_mma_kernel<<<grid, THREADS, SMEM_BYTES>>>(keys, values, q_in, out);
}

// round 13
// speedup vs baseline: 1.4663x; 1.4663x over previous
#include <cuda_runtime.h>
#include <cuda_bf16.h>
#include <cstdint>

// ---------------- problem constants ----------------
#define O_N   3
#define DK    128
#define DV    512
#define BANK  8192
#define QN    4096
#define MQ    64             // queries per block
#define BN    64             // bank tile
#define NV    256            // v columns per pass (vpass = blockIdx.z)
#define NT    128            // bank tiles (8192/64)
#define THREADS 256
// 1/sqrt(128) * log2(e), folded into Q so epilogue is bare ex2
#define QSCALE (0.08838834764831845f * 1.4426950408889634f)

// ---------------- smem layout (double buffered, occupancy 1) ----------------
// strides in bf16 halves; (row_stride_bytes/16) mod 8 odd -> ldmatrix conflict-free
#define QS_STR 136   // 272 B rows
#define KS_STR 136
#define VS_STR 72    // 144 B rows
#define PS_STR 72
#define QS_OFF    0                        // 64*136*2  = 17408
#define KS_OFF(b) (17408 + (b) * 17408)    // 2 bufs -> 52224
#define VS_OFF(b) (52224 + (b) * 36864)    // 2 bufs -> 125952
#define PS_OFF    125952                   // 64*72*2  = 9216 -> 135168
#define LROW_OFF  135168                   // 64 f32   = 256  -> 135424
#define SMEM_BYTES 135424

// ---------------- bf16 scratch (pre-converted once per launch) ----------------
__device__ __nv_bfloat16 g_kT[(size_t)O_N * BANK * DK];   // [o][n][k]  6 MB
__device__ __nv_bfloat16 g_vB[(size_t)O_N * DV * BANK];   // [o][v][n] 24 MB

// ---------------- helpers ----------------
static __device__ __forceinline__ uint32_t s2u(const void* p) {
    uint32_t a;
    asm("{ .reg .u64 t; cvta.to.shared.u64 t, %1; cvt.u32.u64 %0, t; }" : "=r"(a) : "l"(p));
    return a;
}
static __device__ __forceinline__ uint32_t pack2(float lo, float hi) {   // lo -> low half
    uint32_t r;
    asm("cvt.rn.bf16x2.f32 %0, %1, %2;" : "=r"(r) : "f"(hi), "f"(lo));
    return r;
}
static __device__ __forceinline__ float ex2f(float x) {
    float r; asm("ex2.approx.f32 %0, %1;" : "=f"(r) : "f"(x)); return r;
}
static __device__ __forceinline__ void ldsm4(uint32_t* r, uint32_t addr) {
    asm volatile("ldmatrix.sync.aligned.m8n8.x4.shared.b16 {%0,%1,%2,%3}, [%4];"
                 : "=r"(r[0]), "=r"(r[1]), "=r"(r[2]), "=r"(r[3]) : "r"(addr));
}
static __device__ __forceinline__ void mma16816(float* d, const uint32_t* a,
                                                uint32_t b0, uint32_t b1) {
    asm volatile(
        "mma.sync.aligned.m16n8k16.row.col.f32.bf16.bf16.f32 "
        "{%0,%1,%2,%3}, {%4,%5,%6,%7}, {%8,%9}, {%0,%1,%2,%3};"
        : "+f"(d[0]), "+f"(d[1]), "+f"(d[2]), "+f"(d[3])
        : "r"(a[0]), "r"(a[1]), "r"(a[2]), "r"(a[3]), "r"(b0), "r"(b1));
}
static __device__ __forceinline__ void cpa16(uint32_t s, const void* g) {
    asm volatile("cp.async.cg.shared.global [%0], [%1], 16;" :: "r"(s), "l"(g) : "memory");
}

// ---------------- prep: K fp32 [o][k][n] -> bf16 [o][n][k]; V fp32 -> bf16 ----------------
__global__ void prep_kernel(const float* __restrict__ keys, const float* __restrict__ values) {
    const int bid = blockIdx.x, tid = threadIdx.x;
    if (bid < O_N * (BANK / 64)) {
        // K transpose+convert: one 64n x 128k tile
        __shared__ float tile[128][65];
        const int o = bid / (BANK / 64), nt = bid % (BANK / 64), n0 = nt * 64;
        const float* kg = keys + (size_t)o * DK * BANK;
#pragma unroll
        for (int i = 0; i < 8; ++i) {
            int idx = tid + 256 * i;
            int k = idx >> 4, f4 = idx & 15;
            const float4 x = *(const float4*)(kg + (size_t)k * BANK + n0 + f4 * 4);
            tile[k][f4 * 4 + 0] = x.x; tile[k][f4 * 4 + 1] = x.y;
            tile[k][f4 * 4 + 2] = x.z; tile[k][f4 * 4 + 3] = x.w;
        }
        __syncthreads();
        uint32_t* outp = (uint32_t*)g_kT;
#pragma unroll
        for (int i = 0; i < 16; ++i) {
            int u = tid + 256 * i;
            int n = u >> 6, k2 = u & 63;
            outp[(size_t)o * BANK * 64 + (size_t)(n0 + n) * 64 + k2] =
                pack2(tile[2 * k2][n], tile[2 * k2 + 1][n]);
        }
    } else {
        // V convert (layout preserved)
        const int vb = bid - O_N * (BANK / 64);
        const float4* src = (const float4*)values;
        uint2* dst = (uint2*)g_vB;
#pragma unroll
        for (int i = 0; i < 16; ++i) {
            size_t idx = (size_t)vb * 4096 + tid + 256 * i;
            const float4 x = src[idx];
            uint2 p;
            p.x = pack2(x.x, x.y);
            p.y = pack2(x.z, x.w);
            dst[idx] = p;
        }
    }
}
#define PREP_BLOCKS (O_N * (BANK / 64) + (O_N * DV * BANK) / 16384)   // 384 + 768

// ---------------- async tile loader: 12 x 16B cp.async per thread ----------------
static __device__ __forceinline__ void load_tile_async(uint32_t sb, int o, int v0,
                                                       int buf, int t, int tid) {
    const int n0 = t * BN;
    const uint32_t ks = sb + KS_OFF(buf), vs = sb + VS_OFF(buf);
    const __nv_bfloat16* kT = g_kT + (size_t)o * BANK * DK + (size_t)n0 * DK;
    const __nv_bfloat16* vB = g_vB + (size_t)o * DV * BANK + (size_t)v0 * BANK;
    // K tile: 64 rows x 256B (16 chunks/row)
#pragma unroll
    for (int i = 0; i < 4; ++i) {
        int c = tid + THREADS * i;
        int n = c >> 4, k16 = c & 15;
        cpa16(ks + (uint32_t)(n * (KS_STR * 2) + k16 * 16), kT + (size_t)n * DK + k16 * 8);
    }
    // V tile: 256 rows x 128B (8 chunks/row)
#pragma unroll
    for (int i = 0; i < 8; ++i) {
        int c = tid + THREADS * i;
        int v = c >> 3, n16 = c & 7;
        cpa16(vs + (uint32_t)(v * (VS_STR * 2) + n16 * 16), vB + (size_t)v * BANK + n0 + n16 * 8);
    }
    asm volatile("cp.async.commit_group;" ::: "memory");
}

// ---------------- main fused kernel ----------------
__global__ __launch_bounds__(THREADS)
void attn_mma_kernel(const float* __restrict__ q_in, float* __restrict__ out) {
    extern __shared__ unsigned char smem[];
    const uint32_t sb = s2u(smem);
    const int tid = threadIdx.x;
    const int l = tid & 31;
    const int wid = tid >> 5;
    const int mw = wid >> 2;          // 0..1 : 32-query group
    const int nw = wid & 3;           // 0..3 : QK n-group (16) / PV v-group (64)
    const int o = blockIdx.y;
    const int q0 = blockIdx.x * MQ;
    const int v0 = blockIdx.z * NV;

    if (tid < MQ) *(float*)(smem + LROW_OFF + tid * 4) = 0.0f;

    // Q -> Qs[q][k] bf16, scaled (one-time)
    {
        __nv_bfloat16* qs = (__nv_bfloat16*)(smem + QS_OFF);
#pragma unroll
        for (int i = 0; i < 8; ++i) {
            int idx = tid + THREADS * i;
            int k = idx >> 4, q4 = (idx & 15) * 4;
            const float4 x = *(const float4*)(q_in + (size_t)k * QN + q0 + q4);
            qs[(q4 + 0) * QS_STR + k] = __float2bfloat16(x.x * QSCALE);
            qs[(q4 + 1) * QS_STR + k] = __float2bfloat16(x.y * QSCALE);
            qs[(q4 + 2) * QS_STR + k] = __float2bfloat16(x.z * QSCALE);
            qs[(q4 + 3) * QS_STR + k] = __float2bfloat16(x.w * QSCALE);
        }
    }
    load_tile_async(sb, o, v0, 0, 0, tid);
    asm volatile("cp.async.wait_group 0;" ::: "memory");
    __syncthreads();

    float acc[2][8][4];
#pragma unroll
    for (int a = 0; a < 2; ++a)
#pragma unroll
        for (int b = 0; b < 8; ++b)
#pragma unroll
            for (int c = 0; c < 4; ++c) acc[a][b][c] = 0.0f;
    float lsum[4] = {0.f, 0.f, 0.f, 0.f};

    // ldmatrix lane address components
    const int aRow = l & 15;                     // A frags: rows within m16
    const int aKhi = l >> 4;                     // A frags: k-half select
    const int bRow = (l & 7) + ((l >> 4) << 3);  // B frags: rows (n-dim of B^T)
    const int bKhi = (l >> 3) & 1;               // B frags: k-half select

    const uint32_t qsb = sb + QS_OFF + (uint32_t)(((mw * 32 + aRow) * QS_STR + 8 * aKhi) * 2);
    const uint32_t psb = sb + PS_OFF + (uint32_t)(((mw * 32 + aRow) * PS_STR + 8 * aKhi) * 2);
    const int g8 = l >> 2, t2 = (l & 3) * 2;

    for (int g = 0; g < NT; ++g) {
        const int buf = g & 1;
        // ---- issue async loads for tile g+1 into the spare buffer ----
        if (g + 1 < NT) load_tile_async(sb, o, v0, (g + 1) & 1, g + 1, tid);
        // ---- QK: S[64q x 64n] ----
        float sc[2][2][4];
#pragma unroll
        for (int a = 0; a < 2; ++a)
#pragma unroll
            for (int b = 0; b < 2; ++b)
#pragma unroll
                for (int c = 0; c < 4; ++c) sc[a][b][c] = 0.0f;
        {
            const uint32_t ksb = sb + KS_OFF(buf) +
                (uint32_t)(((nw * 16 + bRow) * KS_STR + 8 * bKhi) * 2);
#pragma unroll
            for (int s = 0; s < 8; ++s) {
                uint32_t a0[4], a1[4], b[4];
                ldsm4(a0, qsb + s * 32);
                ldsm4(a1, qsb + 16 * QS_STR * 2 + s * 32);
                ldsm4(b, ksb + s * 32);
                mma16816(sc[0][0], a0, b[0], b[1]);
                mma16816(sc[0][1], a0, b[2], b[3]);
                mma16816(sc[1][0], a1, b[0], b[1]);
                mma16816(sc[1][1], a1, b[2], b[3]);
            }
        }
        // ---- exp -> Ps (bf16), lsum partials ----
#pragma unroll
        for (int mf = 0; mf < 2; ++mf)
#pragma unroll
            for (int nf = 0; nf < 2; ++nf) {
                const int col = nw * 16 + nf * 8 + t2;
                const int row = mw * 32 + mf * 16 + g8;
                float p0 = ex2f(sc[mf][nf][0]), p1 = ex2f(sc[mf][nf][1]);
                *(uint32_t*)(smem + PS_OFF + ((size_t)row * PS_STR + col) * 2) = pack2(p0, p1);
                float p2 = ex2f(sc[mf][nf][2]), p3 = ex2f(sc[mf][nf][3]);
                *(uint32_t*)(smem + PS_OFF + ((size_t)(row + 8) * PS_STR + col) * 2) = pack2(p2, p3);
                lsum[mf * 2 + 0] += p0 + p1;
                lsum[mf * 2 + 1] += p2 + p3;
            }
        __syncthreads();   // Ps visible; Ks(buf) reads done
        // ---- PV: acc += P[64q x 64n] * V[64n x 256v] ----
        {
            const uint32_t vsb = sb + VS_OFF(buf) +
                (uint32_t)(((nw * 64 + bRow) * VS_STR + 8 * bKhi) * 2);
#pragma unroll
            for (int s = 0; s < 4; ++s) {
                uint32_t a0[4], a1[4];
                ldsm4(a0, psb + s * 32);
                ldsm4(a1, psb + 16 * PS_STR * 2 + s * 32);
#pragma unroll
                for (int j = 0; j < 4; ++j) {
                    uint32_t b[4];
                    ldsm4(b, vsb + (uint32_t)(j * 16 * VS_STR * 2) + s * 32);
                    mma16816(acc[0][2 * j],     a0, b[0], b[1]);
                    mma16816(acc[0][2 * j + 1], a0, b[2], b[3]);
                    mma16816(acc[1][2 * j],     a1, b[0], b[1]);
                    mma16816(acc[1][2 * j + 1], a1, b[2], b[3]);
                }
            }
        }
        if (g + 1 < NT) asm volatile("cp.async.wait_group 0;" ::: "memory");
        __syncthreads();
    }

    // ---- reduce l across lanes (t bits) then warps (shared atomics) ----
#pragma unroll
    for (int j = 0; j < 4; ++j) {
        lsum[j] += __shfl_xor_sync(0xffffffffu, lsum[j], 1);
        lsum[j] += __shfl_xor_sync(0xffffffffu, lsum[j], 2);
    }
    if ((l & 3) == 0) {
        float* lrow = (float*)(smem + LROW_OFF);
#pragma unroll
        for (int j = 0; j < 4; ++j)
            atomicAdd(&lrow[mw * 32 + (j >> 1) * 16 + g8 + 8 * (j & 1)], lsum[j]);
    }
    __syncthreads();

    // ---- normalize + store ----
    const float* lrow = (const float*)(smem + LROW_OFF);
    float inv[4];
#pragma unroll
    for (int j = 0; j < 4; ++j)
        inv[j] = 1.0f / lrow[mw * 32 + (j >> 1) * 16 + g8 + 8 * (j & 1)];

    float* ob = out + (size_t)o * 1024 * QN + (size_t)v0 * QN + q0;
#pragma unroll
    for (int mf = 0; mf < 2; ++mf)
#pragma unroll
        for (int nf = 0; nf < 8; ++nf) {
            const int col = nw * 64 + nf * 8 + t2;
            const int r0 = mw * 32 + mf * 16 + g8;
            ob[(size_t)col * QN + r0]           = acc[mf][nf][0] * inv[mf * 2];
            ob[(size_t)(col + 1) * QN + r0]     = acc[mf][nf][1] * inv[mf * 2];
            ob[(size_t)col * QN + r0 + 8]       = acc[mf][nf][2] * inv[mf * 2 + 1];
            ob[(size_t)(col + 1) * QN + r0 + 8] = acc[mf][nf][3] * inv[mf * 2 + 1];
        }
}

// ---------------- q_out broadcast (channels [512,1024) per object) ----------------
__global__ void copy_qout_kernel(const float* __restrict__ qo, float* __restrict__ out) {
    size_t i = (size_t)blockIdx.x * blockDim.x + threadIdx.x;  // over DV*QN/4
    const float4 v = reinterpret_cast<const float4*>(qo)[i];
#pragma unroll
    for (int o = 0; o < O_N; ++o)
        reinterpret_cast<float4*>(out + (size_t)o * 1024 * QN + (size_t)DV * QN)[i] = v;
}

extern "C" void kernel_launch(void* const* d_in, const int* in_sizes, int n_in,
                              void* d_out, int out_size) {
    const float* keys   = (const float*)d_in[0];  // [3,128,8192]
    const float* values = (const float*)d_in[1];  // [3,512,8192]
    const float* q_in   = (const float*)d_in[2];  // [1,128,4096]
    const float* q_out  = (const float*)d_in[3];  // [1,512,4096]
    float* out = (float*)d_out;                   // [1,3,1024,4096]

    (void)cudaFuncSetAttribute(attn_mma_kernel,
                               cudaFuncAttributeMaxDynamicSharedMemorySize, SMEM_BYTES);

    // 3 launches/call: prep(0), copy(1), attn(2) -> ncu "-s 5" lands on attn (index 5).
    prep_kernel<<<PREP_BLOCKS, 256>>>(keys, values);
    copy_qout_kernel<<<(DV * QN / 4) / 256, 256>>>(q_out, out);

    dim3 grid(QN / MQ, O_N, DV / NV);   // 64 x 3 x 2 = 384 blocks
    attn_mma_kernel<<<grid, THREADS, SMEM_BYTES>>>(q_in, out);
}

// round 14
// speedup vs baseline: 1.8204x; 1.2415x over previous
#include <cuda_runtime.h>
#include <cuda_bf16.h>
#include <cstdint>

// ---------------- problem constants ----------------
#define O_N   3
#define DK    128
#define DV    512
#define BANK  8192
#define QN    4096
#define MQ    64             // queries per block
#define BN    64             // bank tile
#define NV    256            // v columns per pass (vpass = blockIdx.z)
#define NT    128            // bank tiles (8192/64)
#define THREADS 256
// 1/sqrt(128) * log2(e), folded into Q so epilogue is bare ex2
#define QSCALE (0.08838834764831845f * 1.4426950408889634f)

// ---------------- smem layout: 98.6 KB -> 2 CTAs/SM ----------------
// strides in bf16 halves; (row_stride_bytes/16) mod 8 odd -> ldmatrix conflict-free
#define QS_STR 136   // 272 B rows
#define KS_STR 136
#define VS_STR 72    // 144 B rows
#define PS_STR 72
#define QS_OFF    0                        // 64*136*2 = 17408
#define KS_OFF(b) (17408 + (b) * 17408)    // x2 -> 52224 (K double buffered)
#define VS_OFF    52224                    // 256*72*2 = 36864 -> 89088 (V single)
#define PS_OFF    89088                    // 64*72*2  = 9216 -> 98304
#define LROW_OFF  98304                    // 64 f32   = 256  -> 98560
#define SMEM_BYTES 98560

// ---------------- bf16 scratch (pre-converted once per launch) ----------------
__device__ __nv_bfloat16 g_kT[(size_t)O_N * BANK * DK];   // [o][n][k]  6 MB
__device__ __nv_bfloat16 g_vB[(size_t)O_N * DV * BANK];   // [o][v][n] 24 MB

// ---------------- helpers ----------------
static __device__ __forceinline__ uint32_t s2u(const void* p) {
    uint32_t a;
    asm("{ .reg .u64 t; cvta.to.shared.u64 t, %1; cvt.u32.u64 %0, t; }" : "=r"(a) : "l"(p));
    return a;
}
static __device__ __forceinline__ uint32_t pack2(float lo, float hi) {   // lo -> low half
    uint32_t r;
    asm("cvt.rn.bf16x2.f32 %0, %1, %2;" : "=r"(r) : "f"(hi), "f"(lo));
    return r;
}
static __device__ __forceinline__ float ex2f(float x) {
    float r; asm("ex2.approx.f32 %0, %1;" : "=f"(r) : "f"(x)); return r;
}
static __device__ __forceinline__ void ldsm4(uint32_t* r, uint32_t addr) {
    asm volatile("ldmatrix.sync.aligned.m8n8.x4.shared.b16 {%0,%1,%2,%3}, [%4];"
                 : "=r"(r[0]), "=r"(r[1]), "=r"(r[2]), "=r"(r[3]) : "r"(addr));
}
static __device__ __forceinline__ void mma16816(float* d, const uint32_t* a,
                                                uint32_t b0, uint32_t b1) {
    asm volatile(
        "mma.sync.aligned.m16n8k16.row.col.f32.bf16.bf16.f32 "
        "{%0,%1,%2,%3}, {%4,%5,%6,%7}, {%8,%9}, {%0,%1,%2,%3};"
        : "+f"(d[0]), "+f"(d[1]), "+f"(d[2]), "+f"(d[3])
        : "r"(a[0]), "r"(a[1]), "r"(a[2]), "r"(a[3]), "r"(b0), "r"(b1));
}
static __device__ __forceinline__ void cpa16(uint32_t s, const void* g) {
    asm volatile("cp.async.cg.shared.global [%0], [%1], 16;" :: "r"(s), "l"(g) : "memory");
}
static __device__ __forceinline__ void cpa_commit() {
    asm volatile("cp.async.commit_group;" ::: "memory");
}
static __device__ __forceinline__ void cpa_wait0() {
    asm volatile("cp.async.wait_group 0;" ::: "memory");
}
static __device__ __forceinline__ void cpa_wait1() {
    asm volatile("cp.async.wait_group 1;" ::: "memory");
}

// ---------------- prep: K fp32 [o][k][n] -> bf16 [o][n][k]; V fp32 -> bf16 ----------------
__global__ void prep_kernel(const float* __restrict__ keys, const float* __restrict__ values) {
    const int bid = blockIdx.x, tid = threadIdx.x;
    if (bid < O_N * (BANK / 64)) {
        // K transpose+convert: one 64n x 128k tile
        __shared__ float tile[128][65];
        const int o = bid / (BANK / 64), nt = bid % (BANK / 64), n0 = nt * 64;
        const float* kg = keys + (size_t)o * DK * BANK;
#pragma unroll
        for (int i = 0; i < 8; ++i) {
            int idx = tid + 256 * i;
            int k = idx >> 4, f4 = idx & 15;
            const float4 x = *(const float4*)(kg + (size_t)k * BANK + n0 + f4 * 4);
            tile[k][f4 * 4 + 0] = x.x; tile[k][f4 * 4 + 1] = x.y;
            tile[k][f4 * 4 + 2] = x.z; tile[k][f4 * 4 + 3] = x.w;
        }
        __syncthreads();
        uint32_t* outp = (uint32_t*)g_kT;
#pragma unroll
        for (int i = 0; i < 16; ++i) {
            int u = tid + 256 * i;
            int n = u >> 6, k2 = u & 63;
            outp[(size_t)o * BANK * 64 + (size_t)(n0 + n) * 64 + k2] =
                pack2(tile[2 * k2][n], tile[2 * k2 + 1][n]);
        }
    } else {
        // V convert (layout preserved)
        const int vb = bid - O_N * (BANK / 64);
        const float4* src = (const float4*)values;
        uint2* dst = (uint2*)g_vB;
#pragma unroll
        for (int i = 0; i < 16; ++i) {
            size_t idx = (size_t)vb * 4096 + tid + 256 * i;
            const float4 x = src[idx];
            uint2 p;
            p.x = pack2(x.x, x.y);
            p.y = pack2(x.z, x.w);
            dst[idx] = p;
        }
    }
}
#define PREP_BLOCKS (O_N * (BANK / 64) + (O_N * DV * BANK) / 16384)   // 384 + 768

// ---------------- async loaders (one commit group per call) ----------------
static __device__ __forceinline__ void load_K_async(uint32_t sb, int o, int buf, int t, int tid) {
    const int n0 = t * BN;
    const uint32_t ks = sb + KS_OFF(buf);
    const __nv_bfloat16* kT = g_kT + (size_t)o * BANK * DK + (size_t)n0 * DK;
#pragma unroll
    for (int i = 0; i < 4; ++i) {
        int c = tid + THREADS * i;
        int n = c >> 4, k16 = c & 15;
        cpa16(ks + (uint32_t)(n * (KS_STR * 2) + k16 * 16), kT + (size_t)n * DK + k16 * 8);
    }
    cpa_commit();
}
static __device__ __forceinline__ void load_V_async(uint32_t sb, int o, int v0, int t, int tid) {
    const int n0 = t * BN;
    const uint32_t vs = sb + VS_OFF;
    const __nv_bfloat16* vB = g_vB + (size_t)o * DV * BANK + (size_t)v0 * BANK;
#pragma unroll
    for (int i = 0; i < 8; ++i) {
        int c = tid + THREADS * i;
        int v = c >> 3, n16 = c & 7;
        cpa16(vs + (uint32_t)(v * (VS_STR * 2) + n16 * 16), vB + (size_t)v * BANK + n0 + n16 * 8);
    }
    cpa_commit();
}

// ---------------- main fused kernel (occupancy 2) ----------------
__global__ __launch_bounds__(THREADS, 2)
void attn_mma_kernel(const float* __restrict__ q_in, float* __restrict__ out) {
    extern __shared__ unsigned char smem[];
    const uint32_t sb = s2u(smem);
    const int tid = threadIdx.x;
    const int l = tid & 31;
    const int wid = tid >> 5;
    const int mw = wid >> 2;          // 0..1 : 32-query group
    const int nw = wid & 3;           // 0..3 : QK n-group (16) / PV v-group (64)
    const int o = blockIdx.y;
    const int q0 = blockIdx.x * MQ;
    const int v0 = blockIdx.z * NV;

    if (tid < MQ) *(float*)(smem + LROW_OFF + tid * 4) = 0.0f;

    // Q -> Qs[q][k] bf16, scaled (one-time)
    {
        __nv_bfloat16* qs = (__nv_bfloat16*)(smem + QS_OFF);
#pragma unroll
        for (int i = 0; i < 8; ++i) {
            int idx = tid + THREADS * i;
            int k = idx >> 4, q4 = (idx & 15) * 4;
            const float4 x = *(const float4*)(q_in + (size_t)k * QN + q0 + q4);
            qs[(q4 + 0) * QS_STR + k] = __float2bfloat16(x.x * QSCALE);
            qs[(q4 + 1) * QS_STR + k] = __float2bfloat16(x.y * QSCALE);
            qs[(q4 + 2) * QS_STR + k] = __float2bfloat16(x.z * QSCALE);
            qs[(q4 + 3) * QS_STR + k] = __float2bfloat16(x.w * QSCALE);
        }
    }
    load_K_async(sb, o, 0, 0, tid);
    load_V_async(sb, o, v0, 0, tid);
    cpa_wait0();
    __syncthreads();

    float acc[2][8][4];
#pragma unroll
    for (int a = 0; a < 2; ++a)
#pragma unroll
        for (int b = 0; b < 8; ++b)
#pragma unroll
            for (int c = 0; c < 4; ++c) acc[a][b][c] = 0.0f;
    float lsum[4] = {0.f, 0.f, 0.f, 0.f};

    // ldmatrix lane address components
    const int aRow = l & 15;                     // A frags: rows within m16
    const int aKhi = l >> 4;                     // A frags: k-half select
    const int bRow = (l & 7) + ((l >> 4) << 3);  // B frags: rows (n-dim of B^T)
    const int bKhi = (l >> 3) & 1;               // B frags: k-half select

    const uint32_t qsb = sb + QS_OFF + (uint32_t)(((mw * 32 + aRow) * QS_STR + 8 * aKhi) * 2);
    const uint32_t psb = sb + PS_OFF + (uint32_t)(((mw * 32 + aRow) * PS_STR + 8 * aKhi) * 2);
    const int g8 = l >> 2, t2 = (l & 3) * 2;

    for (int g = 0; g < NT; ++g) {
        const int buf = g & 1;
        const bool more = (g + 1 < NT);
        // ---- issue K(g+1) into the spare K buffer (read of that buffer ended @ iter g-1) ----
        if (more) load_K_async(sb, o, (g + 1) & 1, g + 1, tid);
        // ---- QK: S[64q x 64n] ----
        float sc[2][2][4];
#pragma unroll
        for (int a = 0; a < 2; ++a)
#pragma unroll
            for (int b = 0; b < 2; ++b)
#pragma unroll
                for (int c = 0; c < 4; ++c) sc[a][b][c] = 0.0f;
        {
            const uint32_t ksb = sb + KS_OFF(buf) +
                (uint32_t)(((nw * 16 + bRow) * KS_STR + 8 * bKhi) * 2);
#pragma unroll
            for (int s = 0; s < 8; ++s) {
                uint32_t a0[4], a1[4], b[4];
                ldsm4(a0, qsb + s * 32);
                ldsm4(a1, qsb + 16 * QS_STR * 2 + s * 32);
                ldsm4(b, ksb + s * 32);
                mma16816(sc[0][0], a0, b[0], b[1]);
                mma16816(sc[0][1], a0, b[2], b[3]);
                mma16816(sc[1][0], a1, b[0], b[1]);
                mma16816(sc[1][1], a1, b[2], b[3]);
            }
        }
        // ---- exp -> Ps (bf16), lsum partials ----
#pragma unroll
        for (int mf = 0; mf < 2; ++mf)
#pragma unroll
            for (int nf = 0; nf < 2; ++nf) {
                const int col = nw * 16 + nf * 8 + t2;
                const int row = mw * 32 + mf * 16 + g8;
                float p0 = ex2f(sc[mf][nf][0]), p1 = ex2f(sc[mf][nf][1]);
                *(uint32_t*)(smem + PS_OFF + ((size_t)row * PS_STR + col) * 2) = pack2(p0, p1);
                float p2 = ex2f(sc[mf][nf][2]), p3 = ex2f(sc[mf][nf][3]);
                *(uint32_t*)(smem + PS_OFF + ((size_t)(row + 8) * PS_STR + col) * 2) = pack2(p2, p3);
                lsum[mf * 2 + 0] += p0 + p1;
                lsum[mf * 2 + 1] += p2 + p3;
            }
        // ---- V(g) completion (issued last iter; latency covered by QK above) ----
        if (more) cpa_wait1(); else cpa_wait0();
        __syncthreads();   // Ps + Vs visible
        // ---- PV: acc += P[64q x 64n] * V[64n x 256v] ----
        {
            const uint32_t vsb = sb + VS_OFF +
                (uint32_t)(((nw * 64 + bRow) * VS_STR + 8 * bKhi) * 2);
#pragma unroll
            for (int s = 0; s < 4; ++s) {
                uint32_t a0[4], a1[4];
                ldsm4(a0, psb + s * 32);
                ldsm4(a1, psb + 16 * PS_STR * 2 + s * 32);
#pragma unroll
                for (int j = 0; j < 4; ++j) {
                    uint32_t b[4];
                    ldsm4(b, vsb + (uint32_t)(j * 16 * VS_STR * 2) + s * 32);
                    mma16816(acc[0][2 * j],     a0, b[0], b[1]);
                    mma16816(acc[0][2 * j + 1], a0, b[2], b[3]);
                    mma16816(acc[1][2 * j],     a1, b[0], b[1]);
                    mma16816(acc[1][2 * j + 1], a1, b[2], b[3]);
                }
            }
        }
        __syncthreads();   // Vs free for overwrite
        if (more) {
            load_V_async(sb, o, v0, g + 1, tid);   // pending: K(g+1), V(g+1)
            cpa_wait1();                            // K(g+1) done (older group)
            __syncthreads();                        // Ks[(g+1)&1] visible
        }
    }

    // ---- reduce l across lanes (t bits) then warps (shared atomics) ----
#pragma unroll
    for (int j = 0; j < 4; ++j) {
        lsum[j] += __shfl_xor_sync(0xffffffffu, lsum[j], 1);
        lsum[j] += __shfl_xor_sync(0xffffffffu, lsum[j], 2);
    }
    if ((l & 3) == 0) {
        float* lrow = (float*)(smem + LROW_OFF);
#pragma unroll
        for (int j = 0; j < 4; ++j)
            atomicAdd(&lrow[mw * 32 + (j >> 1) * 16 + g8 + 8 * (j & 1)], lsum[j]);
    }
    __syncthreads();

    // ---- normalize + store ----
    const float* lrow = (const float*)(smem + LROW_OFF);
    float inv[4];
#pragma unroll
    for (int j = 0; j < 4; ++j)
        inv[j] = 1.0f / lrow[mw * 32 + (j >> 1) * 16 + g8 + 8 * (j & 1)];

    float* ob = out + (size_t)o * 1024 * QN + (size_t)v0 * QN + q0;
#pragma unroll
    for (int mf = 0; mf < 2; ++mf)
#pragma unroll
        for (int nf = 0; nf < 8; ++nf) {
            const int col = nw * 64 + nf * 8 + t2;
            const int r0 = mw * 32 + mf * 16 + g8;
            ob[(size_t)col * QN + r0]           = acc[mf][nf][0] * inv[mf * 2];
            ob[(size_t)(col + 1) * QN + r0]     = acc[mf][nf][1] * inv[mf * 2];
            ob[(size_t)col * QN + r0 + 8]       = acc[mf][nf][2] * inv[mf * 2 + 1];
            ob[(size_t)(col + 1) * QN + r0 + 8] = acc[mf][nf][3] * inv[mf * 2 + 1];
        }
}

// ---------------- q_out broadcast (channels [512,1024) per object) ----------------
__global__ void copy_qout_kernel(const float* __restrict__ qo, float* __restrict__ out) {
    size_t i = (size_t)blockIdx.x * blockDim.x + threadIdx.x;  // over DV*QN/4
    const float4 v = reinterpret_cast<const float4*>(qo)[i];
#pragma unroll
    for (int o = 0; o < O_N; ++o)
        reinterpret_cast<float4*>(out + (size_t)o * 1024 * QN + (size_t)DV * QN)[i] = v;
}

extern "C" void kernel_launch(void* const* d_in, const int* in_sizes, int n_in,
                              void* d_out, int out_size) {
    const float* keys   = (const float*)d_in[0];  // [3,128,8192]
    const float* values = (const float*)d_in[1];  // [3,512,8192]
    const float* q_in   = (const float*)d_in[2];  // [1,128,4096]
    const float* q_out  = (const float*)d_in[3];  // [1,512,4096]
    float* out = (float*)d_out;                   // [1,3,1024,4096]

    (void)cudaFuncSetAttribute(attn_mma_kernel,
                               cudaFuncAttributeMaxDynamicSharedMemorySize, SMEM_BYTES);

    prep_kernel<<<PREP_BLOCKS, 256>>>(keys, values);
    copy_qout_kernel<<<(DV * QN / 4) / 256, 256>>>(q_out, out);

    dim3 grid(QN / MQ, O_N, DV / NV);   // 64 x 3 x 2 = 384 blocks
    attn_mma_kernel<<<grid, THREADS, SMEM_BYTES>>>(q_in, out);
}

// round 15
// speedup vs baseline: 2.0519x; 1.1272x over previous
#include <cuda_runtime.h>
#include <cuda_bf16.h>
#include <cstdint>

// ---------------- problem constants ----------------
#define O_N   3
#define DK    128
#define DV    512
#define BANK  8192
#define QN    4096
#define MQ    64             // queries per block
#define BN    64             // bank tile
#define NV    256            // v columns per pass (vpass = blockIdx.z)
#define NT    128            // total bank tiles (8192/64)
#define NSL   3              // bank slices (wave-quantization fix)
#define THREADS 256
// 1/sqrt(128) * log2(e), folded into Q so epilogue is bare ex2
#define QSCALE (0.08838834764831845f * 1.4426950408889634f)

// ---------------- smem layout: 98.6 KB -> 2 CTAs/SM ----------------
#define QS_STR 136   // 272 B rows
#define KS_STR 136
#define VS_STR 72    // 144 B rows
#define PS_STR 72
#define QS_OFF    0                        // 64*136*2 = 17408
#define KS_OFF(b) (17408 + (b) * 17408)    // x2 -> 52224 (K double buffered)
#define VS_OFF    52224                    // 256*72*2 = 36864 -> 89088 (V single)
#define PS_OFF    89088                    // 64*72*2  = 9216 -> 98304
#define LROW_OFF  98304                    // 64 f32   = 256  -> 98560
#define SMEM_BYTES 98560

// ---------------- device scratch ----------------
__device__ __nv_bfloat16 g_kT[(size_t)O_N * BANK * DK];   // [o][n][k]  6 MB
__device__ __nv_bfloat16 g_vB[(size_t)O_N * DV * BANK];   // [o][v][n] 24 MB
__device__ float g_part[(size_t)NSL * O_N * DV * QN];     // per-slice unnormalized PV (75 MB)
__device__ float g_Lp[(size_t)NSL * O_N * QN];            // per-slice exp-sums

// ---------------- helpers ----------------
static __device__ __forceinline__ uint32_t s2u(const void* p) {
    uint32_t a;
    asm("{ .reg .u64 t; cvta.to.shared.u64 t, %1; cvt.u32.u64 %0, t; }" : "=r"(a) : "l"(p));
    return a;
}
static __device__ __forceinline__ uint32_t pack2(float lo, float hi) {   // lo -> low half
    uint32_t r;
    asm("cvt.rn.bf16x2.f32 %0, %1, %2;" : "=r"(r) : "f"(hi), "f"(lo));
    return r;
}
static __device__ __forceinline__ float ex2f(float x) {
    float r; asm("ex2.approx.f32 %0, %1;" : "=f"(r) : "f"(x)); return r;
}
static __device__ __forceinline__ void ldsm4(uint32_t* r, uint32_t addr) {
    asm volatile("ldmatrix.sync.aligned.m8n8.x4.shared.b16 {%0,%1,%2,%3}, [%4];"
                 : "=r"(r[0]), "=r"(r[1]), "=r"(r[2]), "=r"(r[3]) : "r"(addr));
}
static __device__ __forceinline__ void mma16816(float* d, const uint32_t* a,
                                                uint32_t b0, uint32_t b1) {
    asm volatile(
        "mma.sync.aligned.m16n8k16.row.col.f32.bf16.bf16.f32 "
        "{%0,%1,%2,%3}, {%4,%5,%6,%7}, {%8,%9}, {%0,%1,%2,%3};"
        : "+f"(d[0]), "+f"(d[1]), "+f"(d[2]), "+f"(d[3])
        : "r"(a[0]), "r"(a[1]), "r"(a[2]), "r"(a[3]), "r"(b0), "r"(b1));
}
static __device__ __forceinline__ void cpa16(uint32_t s, const void* g) {
    asm volatile("cp.async.cg.shared.global [%0], [%1], 16;" :: "r"(s), "l"(g) : "memory");
}
static __device__ __forceinline__ void cpa_commit() {
    asm volatile("cp.async.commit_group;" ::: "memory");
}
static __device__ __forceinline__ void cpa_wait0() {
    asm volatile("cp.async.wait_group 0;" ::: "memory");
}
static __device__ __forceinline__ void cpa_wait1() {
    asm volatile("cp.async.wait_group 1;" ::: "memory");
}

// ---------------- prep: K fp32 [o][k][n] -> bf16 [o][n][k]; V fp32 -> bf16 ----------------
__global__ void prep_kernel(const float* __restrict__ keys, const float* __restrict__ values) {
    const int bid = blockIdx.x, tid = threadIdx.x;
    if (bid < O_N * (BANK / 64)) {
        __shared__ float tile[128][65];
        const int o = bid / (BANK / 64), nt = bid % (BANK / 64), n0 = nt * 64;
        const float* kg = keys + (size_t)o * DK * BANK;
#pragma unroll
        for (int i = 0; i < 8; ++i) {
            int idx = tid + 256 * i;
            int k = idx >> 4, f4 = idx & 15;
            const float4 x = *(const float4*)(kg + (size_t)k * BANK + n0 + f4 * 4);
            tile[k][f4 * 4 + 0] = x.x; tile[k][f4 * 4 + 1] = x.y;
            tile[k][f4 * 4 + 2] = x.z; tile[k][f4 * 4 + 3] = x.w;
        }
        __syncthreads();
        uint32_t* outp = (uint32_t*)g_kT;
#pragma unroll
        for (int i = 0; i < 16; ++i) {
            int u = tid + 256 * i;
            int n = u >> 6, k2 = u & 63;
            outp[(size_t)o * BANK * 64 + (size_t)(n0 + n) * 64 + k2] =
                pack2(tile[2 * k2][n], tile[2 * k2 + 1][n]);
        }
    } else {
        const int vb = bid - O_N * (BANK / 64);
        const float4* src = (const float4*)values;
        uint2* dst = (uint2*)g_vB;
#pragma unroll
        for (int i = 0; i < 16; ++i) {
            size_t idx = (size_t)vb * 4096 + tid + 256 * i;
            const float4 x = src[idx];
            uint2 p;
            p.x = pack2(x.x, x.y);
            p.y = pack2(x.z, x.w);
            dst[idx] = p;
        }
    }
}
#define PREP_BLOCKS (O_N * (BANK / 64) + (O_N * DV * BANK) / 16384)   // 384 + 768

// ---------------- async loaders ----------------
static __device__ __forceinline__ void load_K_async(uint32_t sb, int o, int buf, int t, int tid) {
    const int n0 = t * BN;
    const uint32_t ks = sb + KS_OFF(buf);
    const __nv_bfloat16* kT = g_kT + (size_t)o * BANK * DK + (size_t)n0 * DK;
#pragma unroll
    for (int i = 0; i < 4; ++i) {
        int c = tid + THREADS * i;
        int n = c >> 4, k16 = c & 15;
        cpa16(ks + (uint32_t)(n * (KS_STR * 2) + k16 * 16), kT + (size_t)n * DK + k16 * 8);
    }
    cpa_commit();
}
static __device__ __forceinline__ void load_V_async(uint32_t sb, int o, int v0, int t, int tid) {
    const int n0 = t * BN;
    const uint32_t vs = sb + VS_OFF;
    const __nv_bfloat16* vB = g_vB + (size_t)o * DV * BANK + (size_t)v0 * BANK;
#pragma unroll
    for (int i = 0; i < 8; ++i) {
        int c = tid + THREADS * i;
        int v = c >> 3, n16 = c & 7;
        cpa16(vs + (uint32_t)(v * (VS_STR * 2) + n16 * 16), vB + (size_t)v * BANK + n0 + n16 * 8);
    }
    cpa_commit();
}

// ---------------- main fused kernel (occupancy 2, bank-sliced) ----------------
__global__ __launch_bounds__(THREADS, 2)
void attn_mma_kernel(const float* __restrict__ q_in) {
    extern __shared__ unsigned char smem[];
    const uint32_t sb = s2u(smem);
    const int tid = threadIdx.x;
    const int l = tid & 31;
    const int wid = tid >> 5;
    const int mw = wid >> 2;          // 0..1 : 32-query group
    const int nw = wid & 3;           // 0..3 : QK n-group (16) / PV v-group (64)
    const int bx = blockIdx.x;
    const int slice = bx >> 6;                 // 0..2
    const int q0 = (bx & 63) * MQ;
    const int o = blockIdx.y;
    const int v0 = blockIdx.z * NV;
    const int t0 = slice * 43;
    const int t1 = (slice == 2) ? NT : t0 + 43;   // 43 / 43 / 42 tiles

    if (tid < MQ) *(float*)(smem + LROW_OFF + tid * 4) = 0.0f;

    // Q -> Qs[q][k] bf16, scaled (one-time)
    {
        __nv_bfloat16* qs = (__nv_bfloat16*)(smem + QS_OFF);
#pragma unroll
        for (int i = 0; i < 8; ++i) {
            int idx = tid + THREADS * i;
            int k = idx >> 4, q4 = (idx & 15) * 4;
            const float4 x = *(const float4*)(q_in + (size_t)k * QN + q0 + q4);
            qs[(q4 + 0) * QS_STR + k] = __float2bfloat16(x.x * QSCALE);
            qs[(q4 + 1) * QS_STR + k] = __float2bfloat16(x.y * QSCALE);
            qs[(q4 + 2) * QS_STR + k] = __float2bfloat16(x.z * QSCALE);
            qs[(q4 + 3) * QS_STR + k] = __float2bfloat16(x.w * QSCALE);
        }
    }
    load_K_async(sb, o, t0 & 1, t0, tid);
    load_V_async(sb, o, v0, t0, tid);
    cpa_wait0();
    __syncthreads();

    float acc[2][8][4];
#pragma unroll
    for (int a = 0; a < 2; ++a)
#pragma unroll
        for (int b = 0; b < 8; ++b)
#pragma unroll
            for (int c = 0; c < 4; ++c) acc[a][b][c] = 0.0f;
    float lsum[4] = {0.f, 0.f, 0.f, 0.f};

    const int aRow = l & 15;
    const int aKhi = l >> 4;
    const int bRow = (l & 7) + ((l >> 4) << 3);
    const int bKhi = (l >> 3) & 1;

    const uint32_t qsb = sb + QS_OFF + (uint32_t)(((mw * 32 + aRow) * QS_STR + 8 * aKhi) * 2);
    const uint32_t psb = sb + PS_OFF + (uint32_t)(((mw * 32 + aRow) * PS_STR + 8 * aKhi) * 2);
    const int g8 = l >> 2, t2 = (l & 3) * 2;

    for (int g = t0; g < t1; ++g) {
        const int buf = g & 1;
        const bool more = (g + 1 < t1);
        if (more) load_K_async(sb, o, (g + 1) & 1, g + 1, tid);
        // ---- QK ----
        float sc[2][2][4];
#pragma unroll
        for (int a = 0; a < 2; ++a)
#pragma unroll
            for (int b = 0; b < 2; ++b)
#pragma unroll
                for (int c = 0; c < 4; ++c) sc[a][b][c] = 0.0f;
        {
            const uint32_t ksb = sb + KS_OFF(buf) +
                (uint32_t)(((nw * 16 + bRow) * KS_STR + 8 * bKhi) * 2);
#pragma unroll
            for (int s = 0; s < 8; ++s) {
                uint32_t a0[4], a1[4], b[4];
                ldsm4(a0, qsb + s * 32);
                ldsm4(a1, qsb + 16 * QS_STR * 2 + s * 32);
                ldsm4(b, ksb + s * 32);
                mma16816(sc[0][0], a0, b[0], b[1]);
                mma16816(sc[0][1], a0, b[2], b[3]);
                mma16816(sc[1][0], a1, b[0], b[1]);
                mma16816(sc[1][1], a1, b[2], b[3]);
            }
        }
        // ---- exp -> Ps, lsum ----
#pragma unroll
        for (int mf = 0; mf < 2; ++mf)
#pragma unroll
            for (int nf = 0; nf < 2; ++nf) {
                const int col = nw * 16 + nf * 8 + t2;
                const int row = mw * 32 + mf * 16 + g8;
                float p0 = ex2f(sc[mf][nf][0]), p1 = ex2f(sc[mf][nf][1]);
                *(uint32_t*)(smem + PS_OFF + ((size_t)row * PS_STR + col) * 2) = pack2(p0, p1);
                float p2 = ex2f(sc[mf][nf][2]), p3 = ex2f(sc[mf][nf][3]);
                *(uint32_t*)(smem + PS_OFF + ((size_t)(row + 8) * PS_STR + col) * 2) = pack2(p2, p3);
                lsum[mf * 2 + 0] += p0 + p1;
                lsum[mf * 2 + 1] += p2 + p3;
            }
        if (more) cpa_wait1(); else cpa_wait0();
        __syncthreads();   // Ps + Vs visible
        // ---- PV ----
        {
            const uint32_t vsb = sb + VS_OFF +
                (uint32_t)(((nw * 64 + bRow) * VS_STR + 8 * bKhi) * 2);
#pragma unroll
            for (int s = 0; s < 4; ++s) {
                uint32_t a0[4], a1[4];
                ldsm4(a0, psb + s * 32);
                ldsm4(a1, psb + 16 * PS_STR * 2 + s * 32);
#pragma unroll
                for (int j = 0; j < 4; ++j) {
                    uint32_t b[4];
                    ldsm4(b, vsb + (uint32_t)(j * 16 * VS_STR * 2) + s * 32);
                    mma16816(acc[0][2 * j],     a0, b[0], b[1]);
                    mma16816(acc[0][2 * j + 1], a0, b[2], b[3]);
                    mma16816(acc[1][2 * j],     a1, b[0], b[1]);
                    mma16816(acc[1][2 * j + 1], a1, b[2], b[3]);
                }
            }
        }
        __syncthreads();   // Vs free
        if (more) {
            load_V_async(sb, o, v0, g + 1, tid);
            cpa_wait1();
            __syncthreads();
        }
    }

    // ---- reduce l; store per-slice L (vp==0 only) ----
#pragma unroll
    for (int j = 0; j < 4; ++j) {
        lsum[j] += __shfl_xor_sync(0xffffffffu, lsum[j], 1);
        lsum[j] += __shfl_xor_sync(0xffffffffu, lsum[j], 2);
    }
    if ((l & 3) == 0) {
        float* lrow = (float*)(smem + LROW_OFF);
#pragma unroll
        for (int j = 0; j < 4; ++j)
            atomicAdd(&lrow[mw * 32 + (j >> 1) * 16 + g8 + 8 * (j & 1)], lsum[j]);
    }
    __syncthreads();
    if (blockIdx.z == 0 && tid < MQ)
        g_Lp[((size_t)slice * O_N + o) * QN + q0 + tid] = *(float*)(smem + LROW_OFF + tid * 4);

    // ---- store unnormalized partials to g_part ----
    float* ob = g_part + ((size_t)(slice * O_N + o) * DV + v0) * QN + q0;
#pragma unroll
    for (int mf = 0; mf < 2; ++mf)
#pragma unroll
        for (int nf = 0; nf < 8; ++nf) {
            const int col = nw * 64 + nf * 8 + t2;
            const int r0 = mw * 32 + mf * 16 + g8;
            ob[(size_t)col * QN + r0]           = acc[mf][nf][0];
            ob[(size_t)(col + 1) * QN + r0]     = acc[mf][nf][1];
            ob[(size_t)col * QN + r0 + 8]       = acc[mf][nf][2];
            ob[(size_t)(col + 1) * QN + r0 + 8] = acc[mf][nf][3];
        }
}

// ---------------- normalize: out = (sum of 3 slices) / (sum of 3 L) ----------------
__global__ void norm_kernel(float* __restrict__ out) {
    const size_t i = (size_t)blockIdx.x * blockDim.x + threadIdx.x;  // float4 index
    const size_t SL = (size_t)O_N * DV * QN / 4;
    const size_t LS = (size_t)O_N * QN / 4;
    const int q4 = (int)(i & (QN / 4 - 1));
    const size_t rest = i >> 10;
    const int v = (int)(rest & (DV - 1));
    const int o = (int)(rest >> 9);
    const float4* P = (const float4*)g_part;
    const float4 a = P[i], b = P[i + SL], c = P[i + 2 * SL];
    const float4* L = (const float4*)g_Lp;
    const size_t li = (size_t)o * (QN / 4) + q4;
    const float4 l0 = L[li], l1 = L[li + LS], l2 = L[li + 2 * LS];
    float4 r;
    r.x = (a.x + b.x + c.x) / (l0.x + l1.x + l2.x);
    r.y = (a.y + b.y + c.y) / (l0.y + l1.y + l2.y);
    r.z = (a.z + b.z + c.z) / (l0.z + l1.z + l2.z);
    r.w = (a.w + b.w + c.w) / (l0.w + l1.w + l2.w);
    ((float4*)out)[(size_t)o * (1024 * QN / 4) + (size_t)v * (QN / 4) + q4] = r;
}

// ---------------- q_out broadcast (channels [512,1024) per object) ----------------
__global__ void copy_qout_kernel(const float* __restrict__ qo, float* __restrict__ out) {
    size_t i = (size_t)blockIdx.x * blockDim.x + threadIdx.x;
    const float4 v = reinterpret_cast<const float4*>(qo)[i];
#pragma unroll
    for (int o = 0; o < O_N; ++o)
        reinterpret_cast<float4*>(out + (size_t)o * 1024 * QN + (size_t)DV * QN)[i] = v;
}

extern "C" void kernel_launch(void* const* d_in, const int* in_sizes, int n_in,
                              void* d_out, int out_size) {
    const float* keys   = (const float*)d_in[0];  // [3,128,8192]
    const float* values = (const float*)d_in[1];  // [3,512,8192]
    const float* q_in   = (const float*)d_in[2];  // [1,128,4096]
    const float* q_out  = (const float*)d_in[3];  // [1,512,4096]
    float* out = (float*)d_out;                   // [1,3,1024,4096]

    (void)cudaFuncSetAttribute(attn_mma_kernel,
                               cudaFuncAttributeMaxDynamicSharedMemorySize, SMEM_BYTES);

    // 4 launches/call: prep(0), attn(1), norm(2), copy(3) -> ncu "-s 5" lands on attn.
    prep_kernel<<<PREP_BLOCKS, 256>>>(keys, values);

    dim3 grid(64 * NSL, O_N, DV / NV);   // 192 x 3 x 2 = 1152 blocks
    attn_mma_kernel<<<grid, THREADS, SMEM_BYTES>>>(q_in);

    norm_kernel<<<(O_N * DV * QN / 4) / 256, 256>>>(out);
    copy_qout_kernel<<<(DV * QN / 4) / 256, 256>>>(q_out, out);
}